// round 13
// baseline (speedup 1.0000x reference)
#include <cuda_runtime.h>
#include <cstdint>

#define N_NODES 50000
#define N_EDGES 400000
#define N_PATHS 512
#define DIM 64

// ---------------- device scratch (static: no runtime allocation) ----------------
__device__ float g_h0[N_NODES * DIM];            // 12.8 MB
__device__ float g_h1[N_NODES * DIM];            // 12.8 MB
__device__ float g_path[N_PATHS * DIM];          // 128 KB
__device__ int   g_is32;
__device__ int   g_cnt[N_NODES];                 // in-degree counts
__device__ int   g_off[N_NODES + 1];             // CSR offsets
__device__ int   g_cur[N_NODES];                 // fill cursors
__device__ int   g_csr[N_EDGES];                 // src id per (dst-sorted) slot

// ---------------- common helpers ----------------
__device__ __forceinline__ unsigned f2tf32(float f) {
    unsigned u;
    asm("cvt.rna.tf32.f32 %0, %1;" : "=r"(u) : "f"(f));
    return u;
}

__device__ __forceinline__ void mma8(float* c, const unsigned* a, unsigned b0, unsigned b1) {
    asm volatile(
        "mma.sync.aligned.m16n8k8.row.col.f32.tf32.tf32.f32 "
        "{%0,%1,%2,%3}, {%4,%5,%6,%7}, {%8,%9}, {%0,%1,%2,%3};"
        : "+f"(c[0]), "+f"(c[1]), "+f"(c[2]), "+f"(c[3])
        : "r"(a[0]), "r"(a[1]), "r"(a[2]), "r"(a[3]), "r"(b0), "r"(b1));
}

__device__ __forceinline__ void cp16(float* sdst, const float* gsrc) {
    unsigned s = (unsigned)__cvta_generic_to_shared(sdst);
    asm volatile("cp.async.cg.shared.global [%0], [%1], 16;" ::"r"(s), "l"(gsrc));
}

// on-the-fly edge index fetch (handles int32 or int64 payload)
__device__ __forceinline__ void load_edge(const void* ei, int flag, int e,
                                          int& s, int& d) {
    if (flag) {
        const int* p = (const int*)ei;
        s = __ldg(&p[e]);
        d = __ldg(&p[N_EDGES + e]);
    } else {
        const long long* p = (const long long*)ei;
        s = (int)__ldg(&p[e]);
        d = (int)__ldg(&p[N_EDGES + e]);
    }
}

// ---------------- launch 1: init (zero small scratch) + dtype probe (block 0) ----------------
__global__ void init_kernel(int* __restrict__ cnt, float* __restrict__ pemb,
                            int* __restrict__ flag, const int* __restrict__ ei_w) {
    int i = blockIdx.x * blockDim.x + threadIdx.x;
    if (i < N_NODES) cnt[i] = 0;
    if (i < N_PATHS * DIM) pemb[i] = 0.0f;
    if (blockIdx.x == 0) {
        int t = threadIdx.x;
        int nz = 0;
#pragma unroll
        for (int k = 0; k < 16; k++) {
            int idx = t * 16 + k;  // 4096 probed entries
            if (ei_w[2 * idx + 1] != 0) nz = 1;
        }
        int any = __syncthreads_or(nz);
        if (t == 0) *flag = any;
    }
}

// ---------------- launch 2: in-degree histogram ----------------
__global__ void hist_kernel(const void* __restrict__ ei,
                            const int* __restrict__ flagp,
                            int* __restrict__ cnt) {
    int e = blockIdx.x * blockDim.x + threadIdx.x;
    if (e >= N_EDGES) return;
    int s, d;
    load_edge(ei, *flagp, e, s, d);
    atomicAdd(&cnt[d], 1);
}

// ---------------- launch 3: single-block exclusive scan (50k counts) ----------------
#define SCAN_T 1024
#define SCAN_CH 49   // 1024*49 = 50176 >= 50000
__global__ void __launch_bounds__(SCAN_T) scan_kernel(
    const int* __restrict__ cnt, int* __restrict__ off, int* __restrict__ cur) {
    __shared__ int spart[SCAN_T];
    int t = threadIdx.x;
    int lo = t * SCAN_CH;
    int hi = min(lo + SCAN_CH, N_NODES);
    int part = 0;
    for (int i = lo; i < hi; i++) part += cnt[i];
    spart[t] = part;
    __syncthreads();
    // Hillis-Steele inclusive scan
    for (int o = 1; o < SCAN_T; o <<= 1) {
        int v = (t >= o) ? spart[t - o] : 0;
        __syncthreads();
        spart[t] += v;
        __syncthreads();
    }
    int running = spart[t] - part;  // exclusive base
    for (int i = lo; i < hi; i++) {
        off[i] = running;
        cur[i] = running;
        running += cnt[i];
    }
    if (hi == N_NODES && lo < N_NODES) off[N_NODES] = running;
    if (N_NODES == 0 && t == 0) off[0] = 0;
}

// ---------------- launch 4: CSR fill (store src id, keyed by dst) ----------------
__global__ void fill_kernel(const void* __restrict__ ei,
                            const int* __restrict__ flagp,
                            int* __restrict__ cur, int* __restrict__ csr) {
    int e = blockIdx.x * blockDim.x + threadIdx.x;
    if (e >= N_EDGES) return;
    int s, d;
    load_edge(ei, *flagp, e, s, d);
    int pos = atomicAdd(&cur[d], 1);
    csr[pos] = s;
}

// ---------------- SAGE layer: fused CSR pull-aggregation + tf32 mma ----------------
// h = relu([pullmean(x), x] @ [Wl;Wr] + bl)
#define SAGE_AX_STRIDE 132
#define SAGE_W_STRIDE 72
#define SAGE_SMEM_BYTES ((128 * SAGE_AX_STRIDE + 128 * SAGE_W_STRIDE) * 4)

__global__ void __launch_bounds__(256) sage_pull_kernel(
    const int* __restrict__ off, const int* __restrict__ csr,
    const float* __restrict__ x, const float* __restrict__ Wl,
    const float* __restrict__ Wr, const float* __restrict__ bl,
    float* __restrict__ h) {
    extern __shared__ float sm[];
    float* sAX = sm;
    float* sW  = sm + 128 * SAGE_AX_STRIDE;

    int tid = threadIdx.x;
    int lane = tid & 31;
    int warp = tid >> 5;

    for (int i = tid; i < 1024; i += 256) {
        int k = i >> 4, c4 = i & 15;
        float4 wl = ((const float4*)Wl)[i];
        float4 wr = ((const float4*)Wr)[i];
        *(float4*)&sW[k * SAGE_W_STRIDE + c4 * 4] = wl;
        *(float4*)&sW[(k + 64) * SAGE_W_STRIDE + c4 * 4] = wr;
    }

    int bc = (lane & 3) * 2;
    float bias0[8], bias1[8];
#pragma unroll
    for (int ni = 0; ni < 8; ni++) {
        bias0[ni] = __ldg(&bl[ni * 8 + bc]);
        bias1[ni] = __ldg(&bl[ni * 8 + bc + 1]);
    }

    int ntiles = (N_NODES + 127) / 128;
    for (int t = blockIdx.x; t < ntiles; t += gridDim.x) {
        int base = t * 128;
        __syncthreads();
        // stage: pull-aggregate (CSR gather) + self features
        for (int i = tid; i < 2048; i += 256) {
            int r = i >> 4, c4 = i & 15;
            int row = base + r;
            float4 va = make_float4(0.f, 0.f, 0.f, 0.f);
            float4 vx = va;
            if (row < N_NODES) {
                int e0 = __ldg(&off[row]);
                int e1 = __ldg(&off[row + 1]);
                for (int e = e0; e < e1; e++) {
                    int s = __ldg(&csr[e]);
                    float4 v = __ldg((const float4*)x + (size_t)s * 16 + c4);
                    va.x += v.x; va.y += v.y; va.z += v.z; va.w += v.w;
                }
                float iv = 1.0f / fmaxf((float)(e1 - e0), 1.0f);
                va.x *= iv; va.y *= iv; va.z *= iv; va.w *= iv;
                vx = __ldg((const float4*)x + (size_t)row * 16 + c4);
            }
            *(float4*)&sAX[r * SAGE_AX_STRIDE + c4 * 4] = va;
            *(float4*)&sAX[r * SAGE_AX_STRIDE + 64 + c4 * 4] = vx;
        }
        __syncthreads();

        float acc[8][4];
#pragma unroll
        for (int ni = 0; ni < 8; ni++) {
            acc[ni][0] = bias0[ni];
            acc[ni][1] = bias1[ni];
            acc[ni][2] = bias0[ni];
            acc[ni][3] = bias1[ni];
        }

        int rb = warp * 16 + (lane >> 2);
        int nb = lane >> 2;
#pragma unroll
        for (int kk = 0; kk < 128; kk += 8) {
            int kA = kk + (lane & 3);
            unsigned a[4];
            a[0] = f2tf32(sAX[rb * SAGE_AX_STRIDE + kA]);
            a[1] = f2tf32(sAX[(rb + 8) * SAGE_AX_STRIDE + kA]);
            a[2] = f2tf32(sAX[rb * SAGE_AX_STRIDE + kA + 4]);
            a[3] = f2tf32(sAX[(rb + 8) * SAGE_AX_STRIDE + kA + 4]);
#pragma unroll
            for (int ni = 0; ni < 8; ni++) {
                unsigned b0 = f2tf32(sW[kA * SAGE_W_STRIDE + ni * 8 + nb]);
                unsigned b1 = f2tf32(sW[(kA + 4) * SAGE_W_STRIDE + ni * 8 + nb]);
                mma8(acc[ni], a, b0, b1);
            }
        }

        int r0 = base + rb;
#pragma unroll
        for (int ni = 0; ni < 8; ni++) {
            int col = ni * 8 + bc;
            if (r0 < N_NODES) {
                float2 o = make_float2(fmaxf(acc[ni][0], 0.f), fmaxf(acc[ni][1], 0.f));
                *(float2*)&h[(size_t)r0 * 64 + col] = o;
            }
            if (r0 + 8 < N_NODES) {
                float2 o = make_float2(fmaxf(acc[ni][2], 0.f), fmaxf(acc[ni][3], 0.f));
                *(float2*)&h[(size_t)(r0 + 8) * 64 + col] = o;
            }
        }
    }
}

// ---------------- big GEMM (R11-best: tf32 mma, M-split, 2 CTAs/SM) ----------------
// path_emb[512,64] += path_masks[512,K] @ B[K,64], B[k,:] = (h1[src[k]]+h1[dst[k]])*0.5
#define SA_ROWS 256
#define SA_STRIDE 36
#define SB_STRIDE 72
#define SA_FLOATS (SA_ROWS * SA_STRIDE)              // 9216
#define SB_FLOATS (32 * SB_STRIDE)                   // 2304
#define BUF_FLOATS (SA_FLOATS + 2 * SB_FLOATS)       // 13824
#define GEMM_SMEM_BYTES (2 * BUF_FLOATS * 4)         // 110592 (x2 CTAs = 221184/SM)

__device__ __forceinline__ void load_chunk_A(float* sA, const float* __restrict__ A,
                                             int k0, int tid) {
#pragma unroll
    for (int i = 0; i < 8; i++) {
        int f = i * 256 + tid;
        int row = f >> 3;
        int c4 = f & 7;
        cp16(sA + row * SA_STRIDE + c4 * 4,
             A + (size_t)row * N_EDGES + k0 + c4 * 4);
    }
}

__device__ __forceinline__ void gather_chunk_B(float* sB1, float* sB2,
                                               const float* __restrict__ h1,
                                               const void* __restrict__ ei,
                                               int flag, int k0, int tid) {
#pragma unroll
    for (int i = 0; i < 2; i++) {
        int f = i * 256 + tid;
        int e = f >> 4;
        int j = f & 15;
        int s, d;
        load_edge(ei, flag, k0 + e, s, d);
        cp16(sB1 + e * SB_STRIDE + j * 4, h1 + (size_t)s * 64 + j * 4);
        cp16(sB2 + e * SB_STRIDE + j * 4, h1 + (size_t)d * 64 + j * 4);
    }
}

__device__ __forceinline__ void combine_B(float* sB1, const float* sB2, int tid) {
#pragma unroll
    for (int i = 0; i < 2; i++) {
        int f = i * 256 + tid;
        int row = f >> 4;
        int c4 = f & 15;
        float4 a = *(float4*)&sB1[row * SB_STRIDE + c4 * 4];
        float4 b = *(const float4*)&sB2[row * SB_STRIDE + c4 * 4];
        a.x = (a.x + b.x) * 0.5f;
        a.y = (a.y + b.y) * 0.5f;
        a.z = (a.z + b.z) * 0.5f;
        a.w = (a.w + b.w) * 0.5f;
        *(float4*)&sB1[row * SB_STRIDE + c4 * 4] = a;
    }
}

__global__ void __launch_bounds__(256, 2) path_gemm_kernel(
    const float* __restrict__ A, const float* __restrict__ h1,
    const void* __restrict__ ei, const int* __restrict__ flagp,
    float* __restrict__ C) {
    extern __shared__ float sm[];
    float* bufA[2]  = {sm, sm + BUF_FLOATS};
    float* bufB1[2] = {sm + SA_FLOATS, sm + BUF_FLOATS + SA_FLOATS};
    float* bufB2[2] = {sm + SA_FLOATS + SB_FLOATS,
                       sm + BUF_FLOATS + SA_FLOATS + SB_FLOATS};

    int tid = threadIdx.x;
    int lane = tid & 31;
    int warp = tid >> 5;
    int m0 = warp * 32;
    int flag = *flagp;

    int kslice = blockIdx.x >> 1;
    int mbase = (blockIdx.x & 1) * 256;
    const float* Am = A + (size_t)mbase * N_EDGES;

    const int nch = N_EDGES / 32;  // 12500
    int c0 = (int)(((long long)kslice * nch) / 148);
    int c1 = (int)(((long long)(kslice + 1) * nch) / 148);

    float acc[2][8][4] = {};

    load_chunk_A(bufA[0], Am, c0 * 32, tid);
    gather_chunk_B(bufB1[0], bufB2[0], h1, ei, flag, c0 * 32, tid);
    asm volatile("cp.async.commit_group;");
    asm volatile("cp.async.wait_group 0;");
    __syncthreads();
    combine_B(bufB1[0], bufB2[0], tid);
    __syncthreads();

    int buf = 0;
    for (int c = c0; c < c1; ++c) {
        float* cA = bufA[buf];
        float* cB = bufB1[buf];
        bool more = (c + 1 < c1);
        if (more) {
            load_chunk_A(bufA[buf ^ 1], Am, (c + 1) * 32, tid);
            gather_chunk_B(bufB1[buf ^ 1], bufB2[buf ^ 1], h1, ei, flag,
                           (c + 1) * 32, tid);
            asm volatile("cp.async.commit_group;");
        }

#pragma unroll
        for (int kk = 0; kk < 32; kk += 8) {
            unsigned a[2][4];
            int rb = m0 + (lane >> 2);
            int kA = kk + (lane & 3);
#pragma unroll
            for (int mi = 0; mi < 2; mi++) {
                int r = rb + mi * 16;
                a[mi][0] = f2tf32(cA[r * SA_STRIDE + kA]);
                a[mi][1] = f2tf32(cA[(r + 8) * SA_STRIDE + kA]);
                a[mi][2] = f2tf32(cA[r * SA_STRIDE + kA + 4]);
                a[mi][3] = f2tf32(cA[(r + 8) * SA_STRIDE + kA + 4]);
            }
            int nb = lane >> 2;
#pragma unroll
            for (int ni = 0; ni < 8; ni++) {
                unsigned b0 = f2tf32(cB[kA * SB_STRIDE + ni * 8 + nb]);
                unsigned b1 = f2tf32(cB[(kA + 4) * SB_STRIDE + ni * 8 + nb]);
                mma8(acc[0][ni], a[0], b0, b1);
                mma8(acc[1][ni], a[1], b0, b1);
            }
        }

        if (more) {
            asm volatile("cp.async.wait_group 0;");
            __syncthreads();
            combine_B(bufB1[buf ^ 1], bufB2[buf ^ 1], tid);
        }
        __syncthreads();
        buf ^= 1;
    }

#pragma unroll
    for (int mi = 0; mi < 2; mi++) {
        int row = mbase + m0 + mi * 16 + (lane >> 2);
#pragma unroll
        for (int ni = 0; ni < 8; ni++) {
            int col = ni * 8 + 2 * (lane & 3);
            atomicAdd((float2*)&C[row * 64 + col],
                      make_float2(acc[mi][ni][0], acc[mi][ni][1]));
            atomicAdd((float2*)&C[(row + 8) * 64 + col],
                      make_float2(acc[mi][ni][2], acc[mi][ni][3]));
        }
    }
}

// ---------------- readout: out = path_emb @ Wro + bro ----------------
__global__ void readout_kernel(const float* __restrict__ P,
                               const float* __restrict__ W,
                               const float* __restrict__ b,
                               float* __restrict__ out) {
    int p = blockIdx.x;
    int d = threadIdx.x;
    float s = __ldg(&b[d]);
    const float* pr = P + p * 64;
#pragma unroll 16
    for (int k = 0; k < 64; k++) s += __ldg(&pr[k]) * __ldg(&W[k * 64 + d]);
    out[p * 64 + d] = s;
}

// ---------------- launcher ----------------
extern "C" void kernel_launch(void* const* d_in, const int* in_sizes, int n_in,
                              void* d_out, int out_size) {
    (void)in_sizes; (void)n_in; (void)out_size;
    const float* x   = (const float*)d_in[0];
    const void*  ei  = d_in[1];
    const float* pm  = (const float*)d_in[2];
    const float* Wl0 = (const float*)d_in[3];
    const float* Wr0 = (const float*)d_in[4];
    const float* bl0 = (const float*)d_in[5];
    const float* Wl1 = (const float*)d_in[6];
    const float* Wr1 = (const float*)d_in[7];
    const float* bl1 = (const float*)d_in[8];
    const float* Wro = (const float*)d_in[9];
    const float* bro = (const float*)d_in[10];
    float* out       = (float*)d_out;

    float *h0, *h1, *pemb;
    int *flag, *cnt, *off, *cur, *csr;
    cudaGetSymbolAddress((void**)&h0,   g_h0);
    cudaGetSymbolAddress((void**)&h1,   g_h1);
    cudaGetSymbolAddress((void**)&pemb, g_path);
    cudaGetSymbolAddress((void**)&flag, g_is32);
    cudaGetSymbolAddress((void**)&cnt,  g_cnt);
    cudaGetSymbolAddress((void**)&off,  g_off);
    cudaGetSymbolAddress((void**)&cur,  g_cur);
    cudaGetSymbolAddress((void**)&csr,  g_csr);

    cudaFuncSetAttribute(path_gemm_kernel,
                         cudaFuncAttributeMaxDynamicSharedMemorySize, GEMM_SMEM_BYTES);
    cudaFuncSetAttribute(sage_pull_kernel,
                         cudaFuncAttributeMaxDynamicSharedMemorySize, SAGE_SMEM_BYTES);

    // 1: init (zero counters/pemb) + dtype probe
    init_kernel<<<(N_NODES + 255) / 256, 256>>>(cnt, pemb, flag, (const int*)ei);
    // 2: in-degree histogram
    hist_kernel<<<(N_EDGES + 255) / 256, 256>>>(ei, flag, cnt);
    // 3: exclusive scan -> CSR offsets + cursors
    scan_kernel<<<1, SCAN_T>>>(cnt, off, cur);
    // 4: CSR fill
    fill_kernel<<<(N_EDGES + 255) / 256, 256>>>(ei, flag, cur, csr);
    // 5: layer-0 fused pull-aggregate + sage
    sage_pull_kernel<<<391, 256, SAGE_SMEM_BYTES>>>(off, csr, x, Wl0, Wr0, bl0, h0);
    // 6: layer-1 fused pull-aggregate + sage  (ncu -s 5 -c 1 captures this)
    sage_pull_kernel<<<391, 256, SAGE_SMEM_BYTES>>>(off, csr, h0, Wl1, Wr1, bl1, h1);
    // 7: big split-K GEMM (R11-best)
    path_gemm_kernel<<<296, 256, GEMM_SMEM_BYTES>>>(pm, h1, ei, flag, pemb);
    // 8: readout
    readout_kernel<<<N_PATHS, 64>>>(pemb, Wro, bro, out);
}

// round 15
// speedup vs baseline: 1.0743x; 1.0743x over previous
#include <cuda_runtime.h>
#include <cstdint>

#define N_NODES 50000
#define N_EDGES 400000
#define N_PATHS 512
#define DIM 64

// ---------------- device scratch (static: no runtime allocation) ----------------
__device__ float g_agg[N_NODES * DIM];           // 12.8 MB (pull-mean output, reused)
__device__ float g_h0[N_NODES * DIM];            // 12.8 MB
__device__ float g_h1[N_NODES * DIM];            // 12.8 MB
__device__ float g_path[N_PATHS * DIM];          // 128 KB
__device__ int   g_is32;
__device__ int   g_cnt[N_NODES];
__device__ int   g_off[N_NODES + 1];
__device__ int   g_cur[N_NODES];
__device__ int   g_csr[N_EDGES];

// ---------------- common helpers ----------------
__device__ __forceinline__ unsigned f2tf32(float f) {
    unsigned u;
    asm("cvt.rna.tf32.f32 %0, %1;" : "=r"(u) : "f"(f));
    return u;
}

__device__ __forceinline__ void mma8(float* c, const unsigned* a, unsigned b0, unsigned b1) {
    asm volatile(
        "mma.sync.aligned.m16n8k8.row.col.f32.tf32.tf32.f32 "
        "{%0,%1,%2,%3}, {%4,%5,%6,%7}, {%8,%9}, {%0,%1,%2,%3};"
        : "+f"(c[0]), "+f"(c[1]), "+f"(c[2]), "+f"(c[3])
        : "r"(a[0]), "r"(a[1]), "r"(a[2]), "r"(a[3]), "r"(b0), "r"(b1));
}

__device__ __forceinline__ void cp16(float* sdst, const float* gsrc) {
    unsigned s = (unsigned)__cvta_generic_to_shared(sdst);
    asm volatile("cp.async.cg.shared.global [%0], [%1], 16;" ::"r"(s), "l"(gsrc));
}

// on-the-fly edge index fetch (handles int32 or int64 payload)
__device__ __forceinline__ void load_edge(const void* ei, int flag, int e,
                                          int& s, int& d) {
    if (flag) {
        const int* p = (const int*)ei;
        s = __ldg(&p[e]);
        d = __ldg(&p[N_EDGES + e]);
    } else {
        const long long* p = (const long long*)ei;
        s = (int)__ldg(&p[e]);
        d = (int)__ldg(&p[N_EDGES + e]);
    }
}

// ---------------- launch 1: init (zero counters/pemb) + dtype probe (block 0) ----------------
// grid MUST cover N_NODES (cnt) — 196 blocks (R14 bug: used pemb-sized grid).
__global__ void init_kernel(int* __restrict__ cnt, float* __restrict__ pemb,
                            int* __restrict__ flag, const int* __restrict__ ei_w) {
    int i = blockIdx.x * blockDim.x + threadIdx.x;
    if (i < N_NODES) cnt[i] = 0;
    if (i < N_PATHS * DIM) pemb[i] = 0.0f;
    if (blockIdx.x == 0) {
        int t = threadIdx.x;
        int nz = 0;
#pragma unroll
        for (int k = 0; k < 16; k++) {
            int idx = t * 16 + k;  // 4096 probed entries
            if (ei_w[2 * idx + 1] != 0) nz = 1;
        }
        int any = __syncthreads_or(nz);
        if (t == 0) *flag = any;
    }
}

// ---------------- launch 2: in-degree histogram ----------------
__global__ void hist_kernel(const void* __restrict__ ei,
                            const int* __restrict__ flagp,
                            int* __restrict__ cnt) {
    int e = blockIdx.x * blockDim.x + threadIdx.x;
    if (e >= N_EDGES) return;
    int s, d;
    load_edge(ei, *flagp, e, s, d);
    atomicAdd(&cnt[d], 1);
}

// ---------------- launch 3: single-block exclusive scan (50k counts) ----------------
#define SCAN_T 1024
#define SCAN_CH 49   // 1024*49 = 50176 >= 50000
__global__ void __launch_bounds__(SCAN_T) scan_kernel(
    const int* __restrict__ cnt, int* __restrict__ off, int* __restrict__ cur) {
    __shared__ int spart[SCAN_T];
    int t = threadIdx.x;
    int lo = t * SCAN_CH;
    int hi = min(lo + SCAN_CH, N_NODES);
    int part = 0;
    for (int i = lo; i < hi; i++) part += cnt[i];
    spart[t] = part;
    __syncthreads();
    for (int o = 1; o < SCAN_T; o <<= 1) {
        int v = (t >= o) ? spart[t - o] : 0;
        __syncthreads();
        spart[t] += v;
        __syncthreads();
    }
    int running = spart[t] - part;  // exclusive base
    for (int i = lo; i < hi; i++) {
        off[i] = running;
        cur[i] = running;
        running += cnt[i];
    }
    if (hi == N_NODES && lo < N_NODES) off[N_NODES] = running;
}

// ---------------- launch 4: CSR fill (src id keyed by dst) ----------------
__global__ void fill_kernel(const void* __restrict__ ei,
                            const int* __restrict__ flagp,
                            int* __restrict__ cur, int* __restrict__ csr) {
    int e = blockIdx.x * blockDim.x + threadIdx.x;
    if (e >= N_EDGES) return;
    int s, d;
    load_edge(ei, *flagp, e, s, d);
    int pos = atomicAdd(&cur[d], 1);
    csr[pos] = s;
}

// ---------------- pull-mean: agg[n] = mean_{e in CSR[n]} x[csr[e]]  (warp per node) ----------------
__global__ void __launch_bounds__(256) pull_mean_kernel(
    const int* __restrict__ off, const int* __restrict__ csr,
    const float* __restrict__ x, float* __restrict__ agg) {
    int widx = (blockIdx.x * blockDim.x + threadIdx.x) >> 5;
    int lane = threadIdx.x & 31;
    if (widx >= N_NODES) return;
    int e0 = __ldg(&off[widx]);
    int e1 = __ldg(&off[widx + 1]);
    float a0 = 0.f, a1 = 0.f;
    int e = e0;
    // 2x unrolled for MLP (independent gathers per iteration)
    for (; e + 2 <= e1; e += 2) {
        int s0 = __ldg(&csr[e]);
        int s1 = __ldg(&csr[e + 1]);
        float v00 = __ldg(&x[(size_t)s0 * 64 + lane]);
        float v01 = __ldg(&x[(size_t)s0 * 64 + lane + 32]);
        float v10 = __ldg(&x[(size_t)s1 * 64 + lane]);
        float v11 = __ldg(&x[(size_t)s1 * 64 + lane + 32]);
        a0 += v00 + v10;
        a1 += v01 + v11;
    }
    if (e < e1) {
        int s0 = __ldg(&csr[e]);
        a0 += __ldg(&x[(size_t)s0 * 64 + lane]);
        a1 += __ldg(&x[(size_t)s0 * 64 + lane + 32]);
    }
    float iv = 1.0f / fmaxf((float)(e1 - e0), 1.0f);
    agg[(size_t)widx * 64 + lane] = a0 * iv;
    agg[(size_t)widx * 64 + lane + 32] = a1 * iv;
}

// ---------------- SAGE layer via tf32 mma: h = relu([agg, x] @ [Wl;Wr] + bl) ----------------
// (agg is already the neighborhood mean)
#define SAGE_AX_STRIDE 132
#define SAGE_W_STRIDE 72
#define SAGE_SMEM_BYTES ((128 * SAGE_AX_STRIDE + 128 * SAGE_W_STRIDE) * 4)

__global__ void __launch_bounds__(256) sage_mma_kernel(
    const float* __restrict__ agg,
    const float* __restrict__ x, const float* __restrict__ Wl,
    const float* __restrict__ Wr, const float* __restrict__ bl,
    float* __restrict__ h) {
    extern __shared__ float sm[];
    float* sAX = sm;
    float* sW  = sm + 128 * SAGE_AX_STRIDE;

    int tid = threadIdx.x;
    int lane = tid & 31;
    int warp = tid >> 5;

    for (int i = tid; i < 1024; i += 256) {
        int k = i >> 4, c4 = i & 15;
        float4 wl = ((const float4*)Wl)[i];
        float4 wr = ((const float4*)Wr)[i];
        *(float4*)&sW[k * SAGE_W_STRIDE + c4 * 4] = wl;
        *(float4*)&sW[(k + 64) * SAGE_W_STRIDE + c4 * 4] = wr;
    }

    int bc = (lane & 3) * 2;
    float bias0[8], bias1[8];
#pragma unroll
    for (int ni = 0; ni < 8; ni++) {
        bias0[ni] = __ldg(&bl[ni * 8 + bc]);
        bias1[ni] = __ldg(&bl[ni * 8 + bc + 1]);
    }

    int ntiles = (N_NODES + 127) / 128;
    for (int t = blockIdx.x; t < ntiles; t += gridDim.x) {
        int base = t * 128;
        __syncthreads();
        for (int i = tid; i < 2048; i += 256) {
            int r = i >> 4, c4 = i & 15;
            int row = base + r;
            float4 va = make_float4(0.f, 0.f, 0.f, 0.f);
            float4 vx = va;
            if (row < N_NODES) {
                va = __ldg((const float4*)agg + (size_t)row * 16 + c4);
                vx = __ldg((const float4*)x + (size_t)row * 16 + c4);
            }
            *(float4*)&sAX[r * SAGE_AX_STRIDE + c4 * 4] = va;
            *(float4*)&sAX[r * SAGE_AX_STRIDE + 64 + c4 * 4] = vx;
        }
        __syncthreads();

        float acc[8][4];
#pragma unroll
        for (int ni = 0; ni < 8; ni++) {
            acc[ni][0] = bias0[ni];
            acc[ni][1] = bias1[ni];
            acc[ni][2] = bias0[ni];
            acc[ni][3] = bias1[ni];
        }

        int rb = warp * 16 + (lane >> 2);
        int nb = lane >> 2;
#pragma unroll
        for (int kk = 0; kk < 128; kk += 8) {
            int kA = kk + (lane & 3);
            unsigned a[4];
            a[0] = f2tf32(sAX[rb * SAGE_AX_STRIDE + kA]);
            a[1] = f2tf32(sAX[(rb + 8) * SAGE_AX_STRIDE + kA]);
            a[2] = f2tf32(sAX[rb * SAGE_AX_STRIDE + kA + 4]);
            a[3] = f2tf32(sAX[(rb + 8) * SAGE_AX_STRIDE + kA + 4]);
#pragma unroll
            for (int ni = 0; ni < 8; ni++) {
                unsigned b0 = f2tf32(sW[kA * SAGE_W_STRIDE + ni * 8 + nb]);
                unsigned b1 = f2tf32(sW[(kA + 4) * SAGE_W_STRIDE + ni * 8 + nb]);
                mma8(acc[ni], a, b0, b1);
            }
        }

        int r0 = base + rb;
#pragma unroll
        for (int ni = 0; ni < 8; ni++) {
            int col = ni * 8 + bc;
            if (r0 < N_NODES) {
                float2 o = make_float2(fmaxf(acc[ni][0], 0.f), fmaxf(acc[ni][1], 0.f));
                *(float2*)&h[(size_t)r0 * 64 + col] = o;
            }
            if (r0 + 8 < N_NODES) {
                float2 o = make_float2(fmaxf(acc[ni][2], 0.f), fmaxf(acc[ni][3], 0.f));
                *(float2*)&h[(size_t)(r0 + 8) * 64 + col] = o;
            }
        }
    }
}

// ---------------- big GEMM (R11-best: tf32 mma, M-split, 2 CTAs/SM) ----------------
// path_emb[512,64] += path_masks[512,K] @ B[K,64], B[k,:] = (h1[src[k]]+h1[dst[k]])*0.5
#define SA_ROWS 256
#define SA_STRIDE 36
#define SB_STRIDE 72
#define SA_FLOATS (SA_ROWS * SA_STRIDE)              // 9216
#define SB_FLOATS (32 * SB_STRIDE)                   // 2304
#define BUF_FLOATS (SA_FLOATS + 2 * SB_FLOATS)       // 13824
#define GEMM_SMEM_BYTES (2 * BUF_FLOATS * 4)         // 110592 (x2 CTAs = 221184/SM)

__device__ __forceinline__ void load_chunk_A(float* sA, const float* __restrict__ A,
                                             int k0, int tid) {
#pragma unroll
    for (int i = 0; i < 8; i++) {
        int f = i * 256 + tid;
        int row = f >> 3;
        int c4 = f & 7;
        cp16(sA + row * SA_STRIDE + c4 * 4,
             A + (size_t)row * N_EDGES + k0 + c4 * 4);
    }
}

__device__ __forceinline__ void gather_chunk_B(float* sB1, float* sB2,
                                               const float* __restrict__ h1,
                                               const void* __restrict__ ei,
                                               int flag, int k0, int tid) {
#pragma unroll
    for (int i = 0; i < 2; i++) {
        int f = i * 256 + tid;
        int e = f >> 4;
        int j = f & 15;
        int s, d;
        load_edge(ei, flag, k0 + e, s, d);
        cp16(sB1 + e * SB_STRIDE + j * 4, h1 + (size_t)s * 64 + j * 4);
        cp16(sB2 + e * SB_STRIDE + j * 4, h1 + (size_t)d * 64 + j * 4);
    }
}

__device__ __forceinline__ void combine_B(float* sB1, const float* sB2, int tid) {
#pragma unroll
    for (int i = 0; i < 2; i++) {
        int f = i * 256 + tid;
        int row = f >> 4;
        int c4 = f & 15;
        float4 a = *(float4*)&sB1[row * SB_STRIDE + c4 * 4];
        float4 b = *(const float4*)&sB2[row * SB_STRIDE + c4 * 4];
        a.x = (a.x + b.x) * 0.5f;
        a.y = (a.y + b.y) * 0.5f;
        a.z = (a.z + b.z) * 0.5f;
        a.w = (a.w + b.w) * 0.5f;
        *(float4*)&sB1[row * SB_STRIDE + c4 * 4] = a;
    }
}

__global__ void __launch_bounds__(256, 2) path_gemm_kernel(
    const float* __restrict__ A, const float* __restrict__ h1,
    const void* __restrict__ ei, const int* __restrict__ flagp,
    float* __restrict__ C) {
    extern __shared__ float sm[];
    float* bufA[2]  = {sm, sm + BUF_FLOATS};
    float* bufB1[2] = {sm + SA_FLOATS, sm + BUF_FLOATS + SA_FLOATS};
    float* bufB2[2] = {sm + SA_FLOATS + SB_FLOATS,
                       sm + BUF_FLOATS + SA_FLOATS + SB_FLOATS};

    int tid = threadIdx.x;
    int lane = tid & 31;
    int warp = tid >> 5;
    int m0 = warp * 32;
    int flag = *flagp;

    int kslice = blockIdx.x >> 1;
    int mbase = (blockIdx.x & 1) * 256;
    const float* Am = A + (size_t)mbase * N_EDGES;

    const int nch = N_EDGES / 32;  // 12500
    int c0 = (int)(((long long)kslice * nch) / 148);
    int c1 = (int)(((long long)(kslice + 1) * nch) / 148);

    float acc[2][8][4] = {};

    load_chunk_A(bufA[0], Am, c0 * 32, tid);
    gather_chunk_B(bufB1[0], bufB2[0], h1, ei, flag, c0 * 32, tid);
    asm volatile("cp.async.commit_group;");
    asm volatile("cp.async.wait_group 0;");
    __syncthreads();
    combine_B(bufB1[0], bufB2[0], tid);
    __syncthreads();

    int buf = 0;
    for (int c = c0; c < c1; ++c) {
        float* cA = bufA[buf];
        float* cB = bufB1[buf];
        bool more = (c + 1 < c1);
        if (more) {
            load_chunk_A(bufA[buf ^ 1], Am, (c + 1) * 32, tid);
            gather_chunk_B(bufB1[buf ^ 1], bufB2[buf ^ 1], h1, ei, flag,
                           (c + 1) * 32, tid);
            asm volatile("cp.async.commit_group;");
        }

#pragma unroll
        for (int kk = 0; kk < 32; kk += 8) {
            unsigned a[2][4];
            int rb = m0 + (lane >> 2);
            int kA = kk + (lane & 3);
#pragma unroll
            for (int mi = 0; mi < 2; mi++) {
                int r = rb + mi * 16;
                a[mi][0] = f2tf32(cA[r * SA_STRIDE + kA]);
                a[mi][1] = f2tf32(cA[(r + 8) * SA_STRIDE + kA]);
                a[mi][2] = f2tf32(cA[r * SA_STRIDE + kA + 4]);
                a[mi][3] = f2tf32(cA[(r + 8) * SA_STRIDE + kA + 4]);
            }
            int nb = lane >> 2;
#pragma unroll
            for (int ni = 0; ni < 8; ni++) {
                unsigned b0 = f2tf32(cB[kA * SB_STRIDE + ni * 8 + nb]);
                unsigned b1 = f2tf32(cB[(kA + 4) * SB_STRIDE + ni * 8 + nb]);
                mma8(acc[0][ni], a[0], b0, b1);
                mma8(acc[1][ni], a[1], b0, b1);
            }
        }

        if (more) {
            asm volatile("cp.async.wait_group 0;");
            __syncthreads();
            combine_B(bufB1[buf ^ 1], bufB2[buf ^ 1], tid);
        }
        __syncthreads();
        buf ^= 1;
    }

#pragma unroll
    for (int mi = 0; mi < 2; mi++) {
        int row = mbase + m0 + mi * 16 + (lane >> 2);
#pragma unroll
        for (int ni = 0; ni < 8; ni++) {
            int col = ni * 8 + 2 * (lane & 3);
            atomicAdd((float2*)&C[row * 64 + col],
                      make_float2(acc[mi][ni][0], acc[mi][ni][1]));
            atomicAdd((float2*)&C[(row + 8) * 64 + col],
                      make_float2(acc[mi][ni][2], acc[mi][ni][3]));
        }
    }
}

// ---------------- readout: out = path_emb @ Wro + bro ----------------
__global__ void readout_kernel(const float* __restrict__ P,
                               const float* __restrict__ W,
                               const float* __restrict__ b,
                               float* __restrict__ out) {
    int p = blockIdx.x;
    int d = threadIdx.x;
    float s = __ldg(&b[d]);
    const float* pr = P + p * 64;
#pragma unroll 16
    for (int k = 0; k < 64; k++) s += __ldg(&pr[k]) * __ldg(&W[k * 64 + d]);
    out[p * 64 + d] = s;
}

// ---------------- launcher ----------------
extern "C" void kernel_launch(void* const* d_in, const int* in_sizes, int n_in,
                              void* d_out, int out_size) {
    (void)in_sizes; (void)n_in; (void)out_size;
    const float* x   = (const float*)d_in[0];
    const void*  ei  = d_in[1];
    const float* pm  = (const float*)d_in[2];
    const float* Wl0 = (const float*)d_in[3];
    const float* Wr0 = (const float*)d_in[4];
    const float* bl0 = (const float*)d_in[5];
    const float* Wl1 = (const float*)d_in[6];
    const float* Wr1 = (const float*)d_in[7];
    const float* bl1 = (const float*)d_in[8];
    const float* Wro = (const float*)d_in[9];
    const float* bro = (const float*)d_in[10];
    float* out       = (float*)d_out;

    float *agg, *h0, *h1, *pemb;
    int *flag, *cnt, *off, *cur, *csr;
    cudaGetSymbolAddress((void**)&agg,  g_agg);
    cudaGetSymbolAddress((void**)&h0,   g_h0);
    cudaGetSymbolAddress((void**)&h1,   g_h1);
    cudaGetSymbolAddress((void**)&pemb, g_path);
    cudaGetSymbolAddress((void**)&flag, g_is32);
    cudaGetSymbolAddress((void**)&cnt,  g_cnt);
    cudaGetSymbolAddress((void**)&off,  g_off);
    cudaGetSymbolAddress((void**)&cur,  g_cur);
    cudaGetSymbolAddress((void**)&csr,  g_csr);

    cudaFuncSetAttribute(path_gemm_kernel,
                         cudaFuncAttributeMaxDynamicSharedMemorySize, GEMM_SMEM_BYTES);
    cudaFuncSetAttribute(sage_mma_kernel,
                         cudaFuncAttributeMaxDynamicSharedMemorySize, SAGE_SMEM_BYTES);

    // 1: init (zero counters/pemb) + dtype probe — grid covers N_NODES (R14 fix)
    init_kernel<<<(N_NODES + 255) / 256, 256>>>(cnt, pemb, flag, (const int*)ei);
    // 2-4: CSR build (hist -> scan -> fill)
    hist_kernel<<<(N_EDGES + 255) / 256, 256>>>(ei, flag, cnt);
    scan_kernel<<<1, SCAN_T>>>(cnt, off, cur);
    fill_kernel<<<(N_EDGES + 255) / 256, 256>>>(ei, flag, cur, csr);
    // 5: layer-0 pull-mean (warp per node, no atomics)
    pull_mean_kernel<<<(N_NODES * 32 + 255) / 256, 256>>>(off, csr, x, agg);
    // 6: layer-0 sage  (ncu -s 5 -c 1 captures this)
    sage_mma_kernel<<<391, 256, SAGE_SMEM_BYTES>>>(agg, x, Wl0, Wr0, bl0, h0);
    // 7: layer-1 pull-mean
    pull_mean_kernel<<<(N_NODES * 32 + 255) / 256, 256>>>(off, csr, h0, agg);
    // 8: layer-1 sage
    sage_mma_kernel<<<391, 256, SAGE_SMEM_BYTES>>>(agg, h0, Wl1, Wr1, bl1, h1);
    // 9: big split-K GEMM (R11-best)
    path_gemm_kernel<<<296, 256, GEMM_SMEM_BYTES>>>(pm, h1, ei, flag, pemb);
    // 10: readout
    readout_kernel<<<N_PATHS, 64>>>(pemb, Wro, bro, out);
}

// round 16
// speedup vs baseline: 1.0816x; 1.0068x over previous
#include <cuda_runtime.h>
#include <cstdint>

#define N_NODES 50000
#define N_EDGES 400000
#define N_PATHS 512
#define DIM 64

// ---------------- device scratch (static: no runtime allocation) ----------------
__device__ float g_deg[N_NODES];
__device__ float g_agg0[N_NODES * DIM];
__device__ float g_agg1[N_NODES * DIM];
__device__ float g_h0[N_NODES * DIM];
__device__ float g_h1[N_NODES * DIM];
__device__ float g_path[N_PATHS * DIM];
__device__ int   g_is32;

// ---------------- common helpers ----------------
__device__ __forceinline__ unsigned f2tf32(float f) {
    unsigned u;
    asm("cvt.rna.tf32.f32 %0, %1;" : "=r"(u) : "f"(f));
    return u;
}

__device__ __forceinline__ void mma8(float* c, const unsigned* a, unsigned b0, unsigned b1) {
    asm volatile(
        "mma.sync.aligned.m16n8k8.row.col.f32.tf32.tf32.f32 "
        "{%0,%1,%2,%3}, {%4,%5,%6,%7}, {%8,%9}, {%0,%1,%2,%3};"
        : "+f"(c[0]), "+f"(c[1]), "+f"(c[2]), "+f"(c[3])
        : "r"(a[0]), "r"(a[1]), "r"(a[2]), "r"(a[3]), "r"(b0), "r"(b1));
}

__device__ __forceinline__ void cp16(float* sdst, const float* gsrc) {
    unsigned s = (unsigned)__cvta_generic_to_shared(sdst);
    asm volatile("cp.async.cg.shared.global [%0], [%1], 16;" ::"r"(s), "l"(gsrc));
}

// on-the-fly edge index fetch (handles int32 or int64 payload)
__device__ __forceinline__ void load_edge(const void* ei, int flag, int e,
                                          int& s, int& d) {
    if (flag) {
        const int* p = (const int*)ei;
        s = __ldg(&p[e]);
        d = __ldg(&p[N_EDGES + e]);
    } else {
        const long long* p = (const long long*)ei;
        s = (int)__ldg(&p[e]);
        d = (int)__ldg(&p[N_EDGES + e]);
    }
}

// ---------------- launch 1: fused init (zero scratch) + dtype probe (block 0) ----------------
__global__ void init_kernel(float* __restrict__ deg, float* __restrict__ agg0,
                            float* __restrict__ agg1, float* __restrict__ pemb,
                            int* __restrict__ flag, const int* __restrict__ ei_w) {
    int i = blockIdx.x * blockDim.x + threadIdx.x;
    if (i < N_NODES) deg[i] = 0.0f;
    if (i < N_NODES * DIM) { agg0[i] = 0.0f; agg1[i] = 0.0f; }
    if (i < N_PATHS * DIM) pemb[i] = 0.0f;
    if (blockIdx.x == 0) {
        int t = threadIdx.x;
        int nz = 0;
#pragma unroll
        for (int k = 0; k < 16; k++) {
            int idx = t * 16 + k;  // 4096 probed entries
            if (ei_w[2 * idx + 1] != 0) nz = 1;
        }
        int any = __syncthreads_or(nz);
        if (t == 0) *flag = any;
    }
}

// ---------------- scatter-sum: agg[dst] += x[src]; optional degree count ----------------
template <bool WITH_DEG>
__global__ void scatter_kernel(const float* __restrict__ x,
                               const void* __restrict__ ei,
                               const int* __restrict__ flagp,
                               float* __restrict__ agg,
                               float* __restrict__ deg) {
    int idx = blockIdx.x * blockDim.x + threadIdx.x;
    if (idx >= N_EDGES * 16) return;
    int e = idx >> 4;
    int j = idx & 15;
    int flag = *flagp;
    int s, d;
    load_edge(ei, flag, e, s, d);
    if (WITH_DEG && j == 0) atomicAdd(&deg[d], 1.0f);
    float4 v = __ldg((const float4*)x + (size_t)s * 16 + j);
    atomicAdd((float4*)agg + (size_t)d * 16 + j, v);
}

// ---------------- SAGE layer via tf32 mma: h = relu([agg/deg, x] @ [Wl;Wr] + bl) ----------------
#define SAGE_AX_STRIDE 132
#define SAGE_W_STRIDE 72
#define SAGE_SMEM_BYTES ((128 * SAGE_AX_STRIDE + 128 * SAGE_W_STRIDE) * 4)

__global__ void __launch_bounds__(256) sage_mma_kernel(
    const float* __restrict__ agg, const float* __restrict__ deg,
    const float* __restrict__ x, const float* __restrict__ Wl,
    const float* __restrict__ Wr, const float* __restrict__ bl,
    float* __restrict__ h) {
    extern __shared__ float sm[];
    float* sAX = sm;
    float* sW  = sm + 128 * SAGE_AX_STRIDE;

    int tid = threadIdx.x;
    int lane = tid & 31;
    int warp = tid >> 5;

    for (int i = tid; i < 1024; i += 256) {
        int k = i >> 4, c4 = i & 15;
        float4 wl = ((const float4*)Wl)[i];
        float4 wr = ((const float4*)Wr)[i];
        *(float4*)&sW[k * SAGE_W_STRIDE + c4 * 4] = wl;
        *(float4*)&sW[(k + 64) * SAGE_W_STRIDE + c4 * 4] = wr;
    }

    int bc = (lane & 3) * 2;
    float bias0[8], bias1[8];
#pragma unroll
    for (int ni = 0; ni < 8; ni++) {
        bias0[ni] = __ldg(&bl[ni * 8 + bc]);
        bias1[ni] = __ldg(&bl[ni * 8 + bc + 1]);
    }

    int ntiles = (N_NODES + 127) / 128;
    for (int t = blockIdx.x; t < ntiles; t += gridDim.x) {
        int base = t * 128;
        __syncthreads();
        for (int i = tid; i < 2048; i += 256) {
            int r = i >> 4, c4 = i & 15;
            int row = base + r;
            float4 va = make_float4(0.f, 0.f, 0.f, 0.f);
            float4 vx = va;
            if (row < N_NODES) {
                va = ((const float4*)agg)[(size_t)row * 16 + c4];
                float iv = 1.0f / fmaxf(deg[row], 1.0f);
                va.x *= iv; va.y *= iv; va.z *= iv; va.w *= iv;
                vx = ((const float4*)x)[(size_t)row * 16 + c4];
            }
            *(float4*)&sAX[r * SAGE_AX_STRIDE + c4 * 4] = va;
            *(float4*)&sAX[r * SAGE_AX_STRIDE + 64 + c4 * 4] = vx;
        }
        __syncthreads();

        float acc[8][4];
#pragma unroll
        for (int ni = 0; ni < 8; ni++) {
            acc[ni][0] = bias0[ni];
            acc[ni][1] = bias1[ni];
            acc[ni][2] = bias0[ni];
            acc[ni][3] = bias1[ni];
        }

        int rb = warp * 16 + (lane >> 2);
        int nb = lane >> 2;
#pragma unroll
        for (int kk = 0; kk < 128; kk += 8) {
            int kA = kk + (lane & 3);
            unsigned a[4];
            a[0] = f2tf32(sAX[rb * SAGE_AX_STRIDE + kA]);
            a[1] = f2tf32(sAX[(rb + 8) * SAGE_AX_STRIDE + kA]);
            a[2] = f2tf32(sAX[rb * SAGE_AX_STRIDE + kA + 4]);
            a[3] = f2tf32(sAX[(rb + 8) * SAGE_AX_STRIDE + kA + 4]);
#pragma unroll
            for (int ni = 0; ni < 8; ni++) {
                unsigned b0 = f2tf32(sW[kA * SAGE_W_STRIDE + ni * 8 + nb]);
                unsigned b1 = f2tf32(sW[(kA + 4) * SAGE_W_STRIDE + ni * 8 + nb]);
                mma8(acc[ni], a, b0, b1);
            }
        }

        int r0 = base + rb;
#pragma unroll
        for (int ni = 0; ni < 8; ni++) {
            int col = ni * 8 + bc;
            if (r0 < N_NODES) {
                float2 o = make_float2(fmaxf(acc[ni][0], 0.f), fmaxf(acc[ni][1], 0.f));
                *(float2*)&h[(size_t)r0 * 64 + col] = o;
            }
            if (r0 + 8 < N_NODES) {
                float2 o = make_float2(fmaxf(acc[ni][2], 0.f), fmaxf(acc[ni][3], 0.f));
                *(float2*)&h[(size_t)(r0 + 8) * 64 + col] = o;
            }
        }
    }
}

// ---------------- big GEMM (R11 base, single-sync loop + inline B combine) ----------------
// path_emb[512,64] += path_masks[512,K] @ B[K,64], B[k,:] = (h1[src[k]]+h1[dst[k]])*0.5
// grid = 296: (K-slice = bid>>1) x (M-half = bid&1, 256 rows each), 2 CTAs/SM.
// The 0.5*(B1+B2) combine happens inside the fragment loads (LDS+LDS+FADD),
// removing the per-chunk combine pass and one __syncthreads.
#define SA_ROWS 256
#define SA_STRIDE 36
#define SB_STRIDE 72
#define SA_FLOATS (SA_ROWS * SA_STRIDE)              // 9216
#define SB_FLOATS (32 * SB_STRIDE)                   // 2304
#define BUF_FLOATS (SA_FLOATS + 2 * SB_FLOATS)       // 13824
#define GEMM_SMEM_BYTES (2 * BUF_FLOATS * 4)         // 110592 (x2 CTAs = 221184/SM)

__device__ __forceinline__ void load_chunk_A(float* sA, const float* __restrict__ A,
                                             int k0, int tid) {
    // 256 rows x 32 k = 2048 float4, 256 threads -> 8 each
#pragma unroll
    for (int i = 0; i < 8; i++) {
        int f = i * 256 + tid;
        int row = f >> 3;
        int c4 = f & 7;
        cp16(sA + row * SA_STRIDE + c4 * 4,
             A + (size_t)row * N_EDGES + k0 + c4 * 4);
    }
}

// async-gather both endpoint rows of 32 edges into sB1 / sB2 (2 float4/thread each)
__device__ __forceinline__ void gather_chunk_B(float* sB1, float* sB2,
                                               const float* __restrict__ h1,
                                               const void* __restrict__ ei,
                                               int flag, int k0, int tid) {
#pragma unroll
    for (int i = 0; i < 2; i++) {
        int f = i * 256 + tid;
        int e = f >> 4;
        int j = f & 15;
        int s, d;
        load_edge(ei, flag, k0 + e, s, d);
        cp16(sB1 + e * SB_STRIDE + j * 4, h1 + (size_t)s * 64 + j * 4);
        cp16(sB2 + e * SB_STRIDE + j * 4, h1 + (size_t)d * 64 + j * 4);
    }
}

__global__ void __launch_bounds__(256, 2) path_gemm_kernel(
    const float* __restrict__ A, const float* __restrict__ h1,
    const void* __restrict__ ei, const int* __restrict__ flagp,
    float* __restrict__ C) {
    extern __shared__ float sm[];
    float* bufA[2]  = {sm, sm + BUF_FLOATS};
    float* bufB1[2] = {sm + SA_FLOATS, sm + BUF_FLOATS + SA_FLOATS};
    float* bufB2[2] = {sm + SA_FLOATS + SB_FLOATS,
                       sm + BUF_FLOATS + SA_FLOATS + SB_FLOATS};

    int tid = threadIdx.x;
    int lane = tid & 31;
    int warp = tid >> 5;
    int m0 = warp * 32;                 // 8 warps x 32 rows (local)
    int flag = *flagp;

    int kslice = blockIdx.x >> 1;       // 0..147
    int mbase = (blockIdx.x & 1) * 256; // M half
    const float* Am = A + (size_t)mbase * N_EDGES;

    const int nch = N_EDGES / 32;  // 12500
    int c0 = (int)(((long long)kslice * nch) / 148);
    int c1 = (int)(((long long)(kslice + 1) * nch) / 148);

    float acc[2][8][4] = {};

    // prologue: stage chunk c0
    load_chunk_A(bufA[0], Am, c0 * 32, tid);
    gather_chunk_B(bufB1[0], bufB2[0], h1, ei, flag, c0 * 32, tid);
    asm volatile("cp.async.commit_group;");
    asm volatile("cp.async.wait_group 0;");
    __syncthreads();

    int buf = 0;
    for (int c = c0; c < c1; ++c) {
        const float* cA = bufA[buf];
        const float* cB1 = bufB1[buf];
        const float* cB2 = bufB2[buf];
        bool more = (c + 1 < c1);
        if (more) {
            // overlap next chunk's loads with this chunk's compute
            load_chunk_A(bufA[buf ^ 1], Am, (c + 1) * 32, tid);
            gather_chunk_B(bufB1[buf ^ 1], bufB2[buf ^ 1], h1, ei, flag,
                           (c + 1) * 32, tid);
            asm volatile("cp.async.commit_group;");
        }

#pragma unroll
        for (int kk = 0; kk < 32; kk += 8) {
            unsigned a[2][4];
            int rb = m0 + (lane >> 2);
            int kA = kk + (lane & 3);
#pragma unroll
            for (int mi = 0; mi < 2; mi++) {
                int r = rb + mi * 16;
                a[mi][0] = f2tf32(cA[r * SA_STRIDE + kA]);
                a[mi][1] = f2tf32(cA[(r + 8) * SA_STRIDE + kA]);
                a[mi][2] = f2tf32(cA[r * SA_STRIDE + kA + 4]);
                a[mi][3] = f2tf32(cA[(r + 8) * SA_STRIDE + kA + 4]);
            }
            int nb = lane >> 2;
#pragma unroll
            for (int ni = 0; ni < 8; ni++) {
                // inline edge-embedding combine: B = 0.5*(h1[src] + h1[dst])
                int o0 = kA * SB_STRIDE + ni * 8 + nb;
                int o1 = (kA + 4) * SB_STRIDE + ni * 8 + nb;
                unsigned b0 = f2tf32(0.5f * (cB1[o0] + cB2[o0]));
                unsigned b1 = f2tf32(0.5f * (cB1[o1] + cB2[o1]));
                mma8(acc[0][ni], a[0], b0, b1);
                mma8(acc[1][ni], a[1], b0, b1);
            }
        }

        if (more) asm volatile("cp.async.wait_group 0;");
        __syncthreads();  // single sync: loads(c+1) visible, compute(c) done (WAR)
        buf ^= 1;
    }

    // epilogue: accumulate C tile with vector L2 reductions
#pragma unroll
    for (int mi = 0; mi < 2; mi++) {
        int row = mbase + m0 + mi * 16 + (lane >> 2);
#pragma unroll
        for (int ni = 0; ni < 8; ni++) {
            int col = ni * 8 + 2 * (lane & 3);
            atomicAdd((float2*)&C[row * 64 + col],
                      make_float2(acc[mi][ni][0], acc[mi][ni][1]));
            atomicAdd((float2*)&C[(row + 8) * 64 + col],
                      make_float2(acc[mi][ni][2], acc[mi][ni][3]));
        }
    }
}

// ---------------- readout: out = path_emb @ Wro + bro ----------------
__global__ void readout_kernel(const float* __restrict__ P,
                               const float* __restrict__ W,
                               const float* __restrict__ b,
                               float* __restrict__ out) {
    int p = blockIdx.x;
    int d = threadIdx.x;
    float s = __ldg(&b[d]);
    const float* pr = P + p * 64;
#pragma unroll 16
    for (int k = 0; k < 64; k++) s += __ldg(&pr[k]) * __ldg(&W[k * 64 + d]);
    out[p * 64 + d] = s;
}

// ---------------- launcher ----------------
extern "C" void kernel_launch(void* const* d_in, const int* in_sizes, int n_in,
                              void* d_out, int out_size) {
    (void)in_sizes; (void)n_in; (void)out_size;
    const float* x   = (const float*)d_in[0];
    const void*  ei  = d_in[1];
    const float* pm  = (const float*)d_in[2];
    const float* Wl0 = (const float*)d_in[3];
    const float* Wr0 = (const float*)d_in[4];
    const float* bl0 = (const float*)d_in[5];
    const float* Wl1 = (const float*)d_in[6];
    const float* Wr1 = (const float*)d_in[7];
    const float* bl1 = (const float*)d_in[8];
    const float* Wro = (const float*)d_in[9];
    const float* bro = (const float*)d_in[10];
    float* out       = (float*)d_out;

    float *deg, *agg0, *agg1, *h0, *h1, *pemb;
    int *flag;
    cudaGetSymbolAddress((void**)&deg,  g_deg);
    cudaGetSymbolAddress((void**)&agg0, g_agg0);
    cudaGetSymbolAddress((void**)&agg1, g_agg1);
    cudaGetSymbolAddress((void**)&h0,   g_h0);
    cudaGetSymbolAddress((void**)&h1,   g_h1);
    cudaGetSymbolAddress((void**)&pemb, g_path);
    cudaGetSymbolAddress((void**)&flag, g_is32);

    cudaFuncSetAttribute(path_gemm_kernel,
                         cudaFuncAttributeMaxDynamicSharedMemorySize, GEMM_SMEM_BYTES);
    cudaFuncSetAttribute(sage_mma_kernel,
                         cudaFuncAttributeMaxDynamicSharedMemorySize, SAGE_SMEM_BYTES);

    // 1: fused zero/init + dtype probe
    init_kernel<<<(N_NODES * DIM + 255) / 256, 256>>>(deg, agg0, agg1, pemb, flag,
                                                      (const int*)ei);
    // 2: layer-0 scatter (+degree)
    scatter_kernel<true><<<(N_EDGES * 16 + 255) / 256, 256>>>(x, ei, flag, agg0, deg);
    // 3: layer-0 sage
    sage_mma_kernel<<<391, 256, SAGE_SMEM_BYTES>>>(agg0, deg, x, Wl0, Wr0, bl0, h0);
    // 4: layer-1 scatter
    scatter_kernel<false><<<(N_EDGES * 16 + 255) / 256, 256>>>(h0, ei, flag, agg1, deg);
    // 5: layer-1 sage
    sage_mma_kernel<<<391, 256, SAGE_SMEM_BYTES>>>(agg1, deg, h0, Wl1, Wr1, bl1, h1);
    // 6: big split-K GEMM (single-sync mainloop, inline B combine)
    path_gemm_kernel<<<296, 256, GEMM_SMEM_BYTES>>>(pm, h1, ei, flag, pemb);
    // 7: readout
    readout_kernel<<<N_PATHS, 64>>>(pemb, Wro, bro, out);
}

// round 17
// speedup vs baseline: 1.2108x; 1.1195x over previous
#include <cuda_runtime.h>
#include <cstdint>

#define N_NODES 50000
#define N_EDGES 400000
#define N_PATHS 512
#define DIM 64

// ---------------- device scratch (static: no runtime allocation) ----------------
__device__ float g_deg[N_NODES];
__device__ float g_agg0[N_NODES * DIM];
__device__ float g_agg1[N_NODES * DIM];
__device__ float g_h0[N_NODES * DIM];
__device__ float g_h1[N_NODES * DIM];
__device__ float g_path[N_PATHS * DIM];
__device__ int   g_is32;

// ---------------- common helpers ----------------
__device__ __forceinline__ unsigned f2tf32(float f) {
    unsigned u;
    asm("cvt.rna.tf32.f32 %0, %1;" : "=r"(u) : "f"(f));
    return u;
}

__device__ __forceinline__ void mma8(float* c, const unsigned* a, unsigned b0, unsigned b1) {
    asm volatile(
        "mma.sync.aligned.m16n8k8.row.col.f32.tf32.tf32.f32 "
        "{%0,%1,%2,%3}, {%4,%5,%6,%7}, {%8,%9}, {%0,%1,%2,%3};"
        : "+f"(c[0]), "+f"(c[1]), "+f"(c[2]), "+f"(c[3])
        : "r"(a[0]), "r"(a[1]), "r"(a[2]), "r"(a[3]), "r"(b0), "r"(b1));
}

__device__ __forceinline__ void cp16(float* sdst, const float* gsrc) {
    unsigned s = (unsigned)__cvta_generic_to_shared(sdst);
    asm volatile("cp.async.cg.shared.global [%0], [%1], 16;" ::"r"(s), "l"(gsrc));
}

// on-the-fly edge index fetch (handles int32 or int64 payload)
__device__ __forceinline__ void load_edge(const void* ei, int flag, int e,
                                          int& s, int& d) {
    if (flag) {
        const int* p = (const int*)ei;
        s = __ldg(&p[e]);
        d = __ldg(&p[N_EDGES + e]);
    } else {
        const long long* p = (const long long*)ei;
        s = (int)__ldg(&p[e]);
        d = (int)__ldg(&p[N_EDGES + e]);
    }
}

// ---------------- launch 1: fused init (zero scratch) + dtype probe (block 0) ----------------
__global__ void init_kernel(float* __restrict__ deg, float* __restrict__ agg0,
                            float* __restrict__ agg1, float* __restrict__ pemb,
                            int* __restrict__ flag, const int* __restrict__ ei_w) {
    int i = blockIdx.x * blockDim.x + threadIdx.x;
    if (i < N_NODES) deg[i] = 0.0f;
    if (i < N_NODES * DIM) { agg0[i] = 0.0f; agg1[i] = 0.0f; }
    if (i < N_PATHS * DIM) pemb[i] = 0.0f;
    if (blockIdx.x == 0) {
        int t = threadIdx.x;
        int nz = 0;
#pragma unroll
        for (int k = 0; k < 16; k++) {
            int idx = t * 16 + k;  // 4096 probed entries
            if (ei_w[2 * idx + 1] != 0) nz = 1;
        }
        int any = __syncthreads_or(nz);
        if (t == 0) *flag = any;
    }
}

// ---------------- scatter-sum: agg[dst] += x[src]; optional degree count ----------------
template <bool WITH_DEG>
__global__ void scatter_kernel(const float* __restrict__ x,
                               const void* __restrict__ ei,
                               const int* __restrict__ flagp,
                               float* __restrict__ agg,
                               float* __restrict__ deg) {
    int idx = blockIdx.x * blockDim.x + threadIdx.x;
    if (idx >= N_EDGES * 16) return;
    int e = idx >> 4;
    int j = idx & 15;
    int flag = *flagp;
    int s, d;
    load_edge(ei, flag, e, s, d);
    if (WITH_DEG && j == 0) atomicAdd(&deg[d], 1.0f);
    float4 v = __ldg((const float4*)x + (size_t)s * 16 + j);
    atomicAdd((float4*)agg + (size_t)d * 16 + j, v);
}

// ---------------- SAGE layer via tf32 mma: h = relu([agg/deg, x] @ [Wl;Wr] + bl) ----------------
#define SAGE_AX_STRIDE 132
#define SAGE_W_STRIDE 72
#define SAGE_SMEM_BYTES ((128 * SAGE_AX_STRIDE + 128 * SAGE_W_STRIDE) * 4)

__global__ void __launch_bounds__(256) sage_mma_kernel(
    const float* __restrict__ agg, const float* __restrict__ deg,
    const float* __restrict__ x, const float* __restrict__ Wl,
    const float* __restrict__ Wr, const float* __restrict__ bl,
    float* __restrict__ h) {
    extern __shared__ float sm[];
    float* sAX = sm;
    float* sW  = sm + 128 * SAGE_AX_STRIDE;

    int tid = threadIdx.x;
    int lane = tid & 31;
    int warp = tid >> 5;

    for (int i = tid; i < 1024; i += 256) {
        int k = i >> 4, c4 = i & 15;
        float4 wl = ((const float4*)Wl)[i];
        float4 wr = ((const float4*)Wr)[i];
        *(float4*)&sW[k * SAGE_W_STRIDE + c4 * 4] = wl;
        *(float4*)&sW[(k + 64) * SAGE_W_STRIDE + c4 * 4] = wr;
    }

    int bc = (lane & 3) * 2;
    float bias0[8], bias1[8];
#pragma unroll
    for (int ni = 0; ni < 8; ni++) {
        bias0[ni] = __ldg(&bl[ni * 8 + bc]);
        bias1[ni] = __ldg(&bl[ni * 8 + bc + 1]);
    }

    int ntiles = (N_NODES + 127) / 128;
    for (int t = blockIdx.x; t < ntiles; t += gridDim.x) {
        int base = t * 128;
        __syncthreads();
        for (int i = tid; i < 2048; i += 256) {
            int r = i >> 4, c4 = i & 15;
            int row = base + r;
            float4 va = make_float4(0.f, 0.f, 0.f, 0.f);
            float4 vx = va;
            if (row < N_NODES) {
                va = ((const float4*)agg)[(size_t)row * 16 + c4];
                float iv = 1.0f / fmaxf(deg[row], 1.0f);
                va.x *= iv; va.y *= iv; va.z *= iv; va.w *= iv;
                vx = ((const float4*)x)[(size_t)row * 16 + c4];
            }
            *(float4*)&sAX[r * SAGE_AX_STRIDE + c4 * 4] = va;
            *(float4*)&sAX[r * SAGE_AX_STRIDE + 64 + c4 * 4] = vx;
        }
        __syncthreads();

        float acc[8][4];
#pragma unroll
        for (int ni = 0; ni < 8; ni++) {
            acc[ni][0] = bias0[ni];
            acc[ni][1] = bias1[ni];
            acc[ni][2] = bias0[ni];
            acc[ni][3] = bias1[ni];
        }

        int rb = warp * 16 + (lane >> 2);
        int nb = lane >> 2;
#pragma unroll
        for (int kk = 0; kk < 128; kk += 8) {
            int kA = kk + (lane & 3);
            unsigned a[4];
            a[0] = f2tf32(sAX[rb * SAGE_AX_STRIDE + kA]);
            a[1] = f2tf32(sAX[(rb + 8) * SAGE_AX_STRIDE + kA]);
            a[2] = f2tf32(sAX[rb * SAGE_AX_STRIDE + kA + 4]);
            a[3] = f2tf32(sAX[(rb + 8) * SAGE_AX_STRIDE + kA + 4]);
#pragma unroll
            for (int ni = 0; ni < 8; ni++) {
                unsigned b0 = f2tf32(sW[kA * SAGE_W_STRIDE + ni * 8 + nb]);
                unsigned b1 = f2tf32(sW[(kA + 4) * SAGE_W_STRIDE + ni * 8 + nb]);
                mma8(acc[ni], a, b0, b1);
            }
        }

        int r0 = base + rb;
#pragma unroll
        for (int ni = 0; ni < 8; ni++) {
            int col = ni * 8 + bc;
            if (r0 < N_NODES) {
                float2 o = make_float2(fmaxf(acc[ni][0], 0.f), fmaxf(acc[ni][1], 0.f));
                *(float2*)&h[(size_t)r0 * 64 + col] = o;
            }
            if (r0 + 8 < N_NODES) {
                float2 o = make_float2(fmaxf(acc[ni][2], 0.f), fmaxf(acc[ni][3], 0.f));
                *(float2*)&h[(size_t)(r0 + 8) * 64 + col] = o;
            }
        }
    }
}

// ---------------- big GEMM (R11 base; combine moved before the single sync) ----------------
// path_emb[512,64] += path_masks[512,K] @ B[K,64], B[k,:] = (h1[src[k]]+h1[dst[k]])*0.5
// grid = 296: (K-slice = bid>>1) x (M-half = bid&1, 256 rows each), 2 CTAs/SM.
// combine_B runs right after cp.async.wait_group with NO barrier: each thread
// combines exactly the float4s it issued itself (identical f->(e,j) mapping),
// and a thread's own cp.async writes are visible to it after wait_group.
// One __syncthreads per chunk then publishes B(c+1) and closes the WAR.
#define SA_ROWS 256
#define SA_STRIDE 36
#define SB_STRIDE 72
#define SA_FLOATS (SA_ROWS * SA_STRIDE)              // 9216
#define SB_FLOATS (32 * SB_STRIDE)                   // 2304
#define BUF_FLOATS (SA_FLOATS + 2 * SB_FLOATS)       // 13824
#define GEMM_SMEM_BYTES (2 * BUF_FLOATS * 4)         // 110592 (x2 CTAs = 221184/SM)

__device__ __forceinline__ void load_chunk_A(float* sA, const float* __restrict__ A,
                                             int k0, int tid) {
    // 256 rows x 32 k = 2048 float4, 256 threads -> 8 each
#pragma unroll
    for (int i = 0; i < 8; i++) {
        int f = i * 256 + tid;
        int row = f >> 3;
        int c4 = f & 7;
        cp16(sA + row * SA_STRIDE + c4 * 4,
             A + (size_t)row * N_EDGES + k0 + c4 * 4);
    }
}

// async-gather both endpoint rows of 32 edges into sB1 / sB2 (2 float4/thread each)
__device__ __forceinline__ void gather_chunk_B(float* sB1, float* sB2,
                                               const float* __restrict__ h1,
                                               const void* __restrict__ ei,
                                               int flag, int k0, int tid) {
#pragma unroll
    for (int i = 0; i < 2; i++) {
        int f = i * 256 + tid;
        int e = f >> 4;
        int j = f & 15;
        int s, d;
        load_edge(ei, flag, k0 + e, s, d);
        cp16(sB1 + e * SB_STRIDE + j * 4, h1 + (size_t)s * 64 + j * 4);
        cp16(sB2 + e * SB_STRIDE + j * 4, h1 + (size_t)d * 64 + j * 4);
    }
}

// sB1 = 0.5*(sB1 + sB2): thread-local (same mapping as gather_chunk_B)
__device__ __forceinline__ void combine_B(float* sB1, const float* sB2, int tid) {
#pragma unroll
    for (int i = 0; i < 2; i++) {
        int f = i * 256 + tid;
        int row = f >> 4;
        int c4 = f & 15;
        float4 a = *(float4*)&sB1[row * SB_STRIDE + c4 * 4];
        float4 b = *(const float4*)&sB2[row * SB_STRIDE + c4 * 4];
        a.x = (a.x + b.x) * 0.5f;
        a.y = (a.y + b.y) * 0.5f;
        a.z = (a.z + b.z) * 0.5f;
        a.w = (a.w + b.w) * 0.5f;
        *(float4*)&sB1[row * SB_STRIDE + c4 * 4] = a;
    }
}

__global__ void __launch_bounds__(256, 2) path_gemm_kernel(
    const float* __restrict__ A, const float* __restrict__ h1,
    const void* __restrict__ ei, const int* __restrict__ flagp,
    float* __restrict__ C) {
    extern __shared__ float sm[];
    float* bufA[2]  = {sm, sm + BUF_FLOATS};
    float* bufB1[2] = {sm + SA_FLOATS, sm + BUF_FLOATS + SA_FLOATS};
    float* bufB2[2] = {sm + SA_FLOATS + SB_FLOATS,
                       sm + BUF_FLOATS + SA_FLOATS + SB_FLOATS};

    int tid = threadIdx.x;
    int lane = tid & 31;
    int warp = tid >> 5;
    int m0 = warp * 32;                 // 8 warps x 32 rows (local)
    int flag = *flagp;

    int kslice = blockIdx.x >> 1;       // 0..147
    int mbase = (blockIdx.x & 1) * 256; // M half
    const float* Am = A + (size_t)mbase * N_EDGES;

    const int nch = N_EDGES / 32;  // 12500
    int c0 = (int)(((long long)kslice * nch) / 148);
    int c1 = (int)(((long long)(kslice + 1) * nch) / 148);

    float acc[2][8][4] = {};

    // prologue: stage + combine chunk c0
    load_chunk_A(bufA[0], Am, c0 * 32, tid);
    gather_chunk_B(bufB1[0], bufB2[0], h1, ei, flag, c0 * 32, tid);
    asm volatile("cp.async.commit_group;");
    asm volatile("cp.async.wait_group 0;");
    combine_B(bufB1[0], bufB2[0], tid);   // thread-local: own cp.async data
    __syncthreads();

    int buf = 0;
    for (int c = c0; c < c1; ++c) {
        const float* cA = bufA[buf];
        const float* cB = bufB1[buf];
        bool more = (c + 1 < c1);
        if (more) {
            // overlap next chunk's loads with this chunk's compute
            load_chunk_A(bufA[buf ^ 1], Am, (c + 1) * 32, tid);
            gather_chunk_B(bufB1[buf ^ 1], bufB2[buf ^ 1], h1, ei, flag,
                           (c + 1) * 32, tid);
            asm volatile("cp.async.commit_group;");
        }

#pragma unroll
        for (int kk = 0; kk < 32; kk += 8) {
            unsigned a[2][4];
            int rb = m0 + (lane >> 2);
            int kA = kk + (lane & 3);
#pragma unroll
            for (int mi = 0; mi < 2; mi++) {
                int r = rb + mi * 16;
                a[mi][0] = f2tf32(cA[r * SA_STRIDE + kA]);
                a[mi][1] = f2tf32(cA[(r + 8) * SA_STRIDE + kA]);
                a[mi][2] = f2tf32(cA[r * SA_STRIDE + kA + 4]);
                a[mi][3] = f2tf32(cA[(r + 8) * SA_STRIDE + kA + 4]);
            }
            int nb = lane >> 2;
#pragma unroll
            for (int ni = 0; ni < 8; ni++) {
                unsigned b0 = f2tf32(cB[kA * SB_STRIDE + ni * 8 + nb]);
                unsigned b1 = f2tf32(cB[(kA + 4) * SB_STRIDE + ni * 8 + nb]);
                mma8(acc[0][ni], a[0], b0, b1);
                mma8(acc[1][ni], a[1], b0, b1);
            }
        }

        if (more) {
            asm volatile("cp.async.wait_group 0;");
            // combine B(c+1): thread-local data (no barrier needed before);
            // writes go to the OTHER buffer, so no race with compute(c) readers.
            combine_B(bufB1[buf ^ 1], bufB2[buf ^ 1], tid);
        }
        __syncthreads();  // publish combined B(c+1) + WAR on buffers
        buf ^= 1;
    }

    // epilogue: accumulate C tile with vector L2 reductions
#pragma unroll
    for (int mi = 0; mi < 2; mi++) {
        int row = mbase + m0 + mi * 16 + (lane >> 2);
#pragma unroll
        for (int ni = 0; ni < 8; ni++) {
            int col = ni * 8 + 2 * (lane & 3);
            atomicAdd((float2*)&C[row * 64 + col],
                      make_float2(acc[mi][ni][0], acc[mi][ni][1]));
            atomicAdd((float2*)&C[(row + 8) * 64 + col],
                      make_float2(acc[mi][ni][2], acc[mi][ni][3]));
        }
    }
}

// ---------------- readout: out = path_emb @ Wro + bro ----------------
__global__ void readout_kernel(const float* __restrict__ P,
                               const float* __restrict__ W,
                               const float* __restrict__ b,
                               float* __restrict__ out) {
    int p = blockIdx.x;
    int d = threadIdx.x;
    float s = __ldg(&b[d]);
    const float* pr = P + p * 64;
#pragma unroll 16
    for (int k = 0; k < 64; k++) s += __ldg(&pr[k]) * __ldg(&W[k * 64 + d]);
    out[p * 64 + d] = s;
}

// ---------------- launcher ----------------
extern "C" void kernel_launch(void* const* d_in, const int* in_sizes, int n_in,
                              void* d_out, int out_size) {
    (void)in_sizes; (void)n_in; (void)out_size;
    const float* x   = (const float*)d_in[0];
    const void*  ei  = d_in[1];
    const float* pm  = (const float*)d_in[2];
    const float* Wl0 = (const float*)d_in[3];
    const float* Wr0 = (const float*)d_in[4];
    const float* bl0 = (const float*)d_in[5];
    const float* Wl1 = (const float*)d_in[6];
    const float* Wr1 = (const float*)d_in[7];
    const float* bl1 = (const float*)d_in[8];
    const float* Wro = (const float*)d_in[9];
    const float* bro = (const float*)d_in[10];
    float* out       = (float*)d_out;

    float *deg, *agg0, *agg1, *h0, *h1, *pemb;
    int *flag;
    cudaGetSymbolAddress((void**)&deg,  g_deg);
    cudaGetSymbolAddress((void**)&agg0, g_agg0);
    cudaGetSymbolAddress((void**)&agg1, g_agg1);
    cudaGetSymbolAddress((void**)&h0,   g_h0);
    cudaGetSymbolAddress((void**)&h1,   g_h1);
    cudaGetSymbolAddress((void**)&pemb, g_path);
    cudaGetSymbolAddress((void**)&flag, g_is32);

    cudaFuncSetAttribute(path_gemm_kernel,
                         cudaFuncAttributeMaxDynamicSharedMemorySize, GEMM_SMEM_BYTES);
    cudaFuncSetAttribute(sage_mma_kernel,
                         cudaFuncAttributeMaxDynamicSharedMemorySize, SAGE_SMEM_BYTES);

    // 1: fused zero/init + dtype probe
    init_kernel<<<(N_NODES * DIM + 255) / 256, 256>>>(deg, agg0, agg1, pemb, flag,
                                                      (const int*)ei);
    // 2: layer-0 scatter (+degree)
    scatter_kernel<true><<<(N_EDGES * 16 + 255) / 256, 256>>>(x, ei, flag, agg0, deg);
    // 3: layer-0 sage
    sage_mma_kernel<<<391, 256, SAGE_SMEM_BYTES>>>(agg0, deg, x, Wl0, Wr0, bl0, h0);
    // 4: layer-1 scatter
    scatter_kernel<false><<<(N_EDGES * 16 + 255) / 256, 256>>>(h0, ei, flag, agg1, deg);
    // 5: layer-1 sage
    sage_mma_kernel<<<391, 256, SAGE_SMEM_BYTES>>>(agg1, deg, h0, Wl1, Wr1, bl1, h1);
    // 6: big split-K GEMM (single-sync chunk tail, thread-local combine)
    path_gemm_kernel<<<296, 256, GEMM_SMEM_BYTES>>>(pm, h1, ei, flag, pemb);
    // 7: readout
    readout_kernel<<<N_PATHS, 64>>>(pemb, Wro, bro, out);
}